// round 16
// baseline (speedup 1.0000x reference)
#include <cuda_runtime.h>
#include <cuda_bf16.h>
#include <cuda_fp8.h>
#include <cstdint>
#include <cstddef>

// ---------------------------------------------------------------------------
// Problem constants.  ALL in/out buffers are FLOAT32 carriers of bf16 values.
// ---------------------------------------------------------------------------
#define NROWS 32768
#define KDIM  2048
#define ODIM  2048

// GEMM tiling: 256x128 CTA tile, 512 threads, 16 warps (4 M x 4 N, warp tile
// 64x32), 1 CTA/SM (still 4 warps/SMSP). Cuts smem reads/tensor-cycle to 0.92
// vs 1.0 for the 128x128 2-CTA config (A redundancy amortized over bigger M).
#define TM 256
#define TN 128
#define KC 64
#define STAGES 3
#define NCHUNK (KDIM / KC)      // 32
#define THREADS 512

#define RS 144
#define STAGE_A_BYTES (TM * RS)                         // 36864
#define STAGE_B_BYTES (TN * RS)                         // 18432
#define STAGE_BYTES   (STAGE_A_BYTES + STAGE_B_BYTES)   // 55296
#define SMEM_DYN      (STAGES * STAGE_BYTES)            // 165888 (1 CTA/SM)

// bf16 scratch: quantized x (134MB) and converted W (8MB)
__device__ __nv_bfloat16 g_xq[(size_t)NROWS * KDIM];
__device__ __nv_bfloat16 g_wb[(size_t)ODIM * KDIM];

#define XUNITS ((long)NROWS * KDIM / 8)   // 8388608 8-f32 units
#define WUNITS ((long)ODIM * KDIM / 8)    // 524288
#define TUNITS (XUNITS + WUNITS)

// ---------------------------------------------------------------------------
// helpers
// ---------------------------------------------------------------------------
__device__ __forceinline__ uint32_t smem_u32(const void* p) {
    uint32_t a;
    asm("{ .reg .u64 t; cvta.to.shared.u64 t, %1; cvt.u32.u64 %0, t; }"
        : "=r"(a) : "l"(p));
    return a;
}

__device__ __forceinline__ void cp16(uint32_t dst_smem, const void* src) {
    asm volatile("cp.async.cg.shared.global [%0], [%1], 16;"
                 :: "r"(dst_smem), "l"(__cvta_generic_to_global(src)) : "memory");
}

__device__ __forceinline__ void ldsm4(uint32_t (&r)[4], uint32_t addr) {
    asm volatile("ldmatrix.sync.aligned.m8n8.x4.shared.b16 {%0,%1,%2,%3}, [%4];"
                 : "=r"(r[0]), "=r"(r[1]), "=r"(r[2]), "=r"(r[3]) : "r"(addr));
}

__device__ __forceinline__ void mma16816(float (&d)[4], const uint32_t (&a)[4],
                                         uint32_t b0, uint32_t b1) {
    asm volatile(
        "mma.sync.aligned.m16n8k16.row.col.f32.bf16.bf16.f32 "
        "{%0,%1,%2,%3}, {%4,%5,%6,%7}, {%8,%9}, {%0,%1,%2,%3};"
        : "+f"(d[0]), "+f"(d[1]), "+f"(d[2]), "+f"(d[3])
        : "r"(a[0]), "r"(a[1]), "r"(a[2]), "r"(a[3]), "r"(b0), "r"(b1));
}

// Packed bf16x2 from two floats
__device__ __forceinline__ uint32_t bf16x2_f32(float lo, float hi) {
    uint32_t r;
    asm("cvt.rn.bf16x2.f32 %0, %1, %2;" : "=r"(r) : "f"(hi), "f"(lo));
    return r;
}

// Fast quant of 2 elements (scale == 1.0): f32 -> e4m3(satfinite) -> bf16x2.
__device__ __forceinline__ uint32_t qdq2_s1(float lo, float hi) {
    uint16_t p8;
    asm("cvt.rn.satfinite.e4m3x2.f32 %0, %1, %2;" : "=h"(p8) : "f"(hi), "f"(lo));
    uint32_t h2;
    asm("cvt.rn.f16x2.e4m3x2 %0, %1;" : "=r"(h2) : "h"(p8));
    __half2 h = *reinterpret_cast<__half2*>(&h2);
    return bf16x2_f32(__half2float(__low2half(h)), __half2float(__high2half(h)));
}

// Exact general-scale chain (reference-faithful)
__device__ __forceinline__ __nv_bfloat16 qdq_gen(float v, float sbf, __nv_bfloat16 sb) {
    float xb = __bfloat162float(__float2bfloat16(v));
    float xs = __bfloat162float(__float2bfloat16(xb / sbf));
    __nv_fp8_storage_t q = __nv_cvt_float_to_fp8(xs, __NV_SATFINITE, __NV_E4M3);
    __half_raw hr = __nv_cvt_fp8_to_halfraw(q, __NV_E4M3);
    return __hmul(__float2bfloat16(__half2float(__half(hr))), sb);
}

// ---------------------------------------------------------------------------
// Kernel 1: merged prepass (x quant + W convert), units of 8 f32.
// ---------------------------------------------------------------------------
__global__ void __launch_bounds__(256) prep_kernel(const float4* __restrict__ x,
                                                   const float4* __restrict__ w,
                                                   const float* __restrict__ scale,
                                                   uint4* __restrict__ xq,
                                                   uint4* __restrict__ wb) {
    const __nv_bfloat16 sb = __float2bfloat16(scale[0]);
    const float sbf = __bfloat162float(sb);
    const bool s1 = (sbf == 1.0f);
    long i = (long)blockIdx.x * blockDim.x + threadIdx.x;
    const long stride = (long)gridDim.x * blockDim.x;
    for (; i < TUNITS; i += stride) {
        if (i < XUNITS) {
            float4 v0 = x[2 * i], v1 = x[2 * i + 1];
            uint4 o;
            if (s1) {
                o.x = qdq2_s1(v0.x, v0.y);
                o.y = qdq2_s1(v0.z, v0.w);
                o.z = qdq2_s1(v1.x, v1.y);
                o.w = qdq2_s1(v1.z, v1.w);
            } else {
                __nv_bfloat162 p0 = __halves2bfloat162(qdq_gen(v0.x, sbf, sb),
                                                       qdq_gen(v0.y, sbf, sb));
                __nv_bfloat162 p1 = __halves2bfloat162(qdq_gen(v0.z, sbf, sb),
                                                       qdq_gen(v0.w, sbf, sb));
                __nv_bfloat162 p2 = __halves2bfloat162(qdq_gen(v1.x, sbf, sb),
                                                       qdq_gen(v1.y, sbf, sb));
                __nv_bfloat162 p3 = __halves2bfloat162(qdq_gen(v1.z, sbf, sb),
                                                       qdq_gen(v1.w, sbf, sb));
                o.x = *reinterpret_cast<uint32_t*>(&p0);
                o.y = *reinterpret_cast<uint32_t*>(&p1);
                o.z = *reinterpret_cast<uint32_t*>(&p2);
                o.w = *reinterpret_cast<uint32_t*>(&p3);
            }
            xq[i] = o;
        } else {
            long j = i - XUNITS;
            float4 v0 = w[2 * j], v1 = w[2 * j + 1];
            uint4 o;
            o.x = bf16x2_f32(v0.x, v0.y);
            o.y = bf16x2_f32(v0.z, v0.w);
            o.z = bf16x2_f32(v1.x, v1.y);
            o.w = bf16x2_f32(v1.z, v1.w);
            wb[j] = o;
        }
    }
}

// ---------------------------------------------------------------------------
// Kernel 2: GEMM, 256x128 CTA tile, inner loop identical to r11 (fragment
// software-pipelining: B double-buffered, A rotated in place).
// ---------------------------------------------------------------------------
__device__ __forceinline__ void load_chunk(uint32_t st, const __nv_bfloat16* A,
                                           const __nv_bfloat16* W,
                                           int m0, int n0, int k0, int tid) {
    // A: 256 rows x 8 16B-units = 2048 units, 4 per thread (512 threads)
#pragma unroll
    for (int t = 0; t < 4; t++) {
        int u = tid + t * THREADS;
        int row = u >> 3, c = u & 7;
        cp16(st + (uint32_t)(row * RS + c * 16),
             A + (size_t)(m0 + row) * KDIM + (size_t)(k0 + c * 8));
    }
    // B: 128 rows x 8 units = 1024 units, 2 per thread
#pragma unroll
    for (int t = 0; t < 2; t++) {
        int u = tid + t * THREADS;
        int row = u >> 3, c = u & 7;
        cp16(st + STAGE_A_BYTES + (uint32_t)(row * RS + c * 16),
             W + (size_t)(n0 + row) * KDIM + (size_t)(k0 + c * 8));
    }
}

__global__ void __launch_bounds__(THREADS, 1) gemm_kernel(
    const __nv_bfloat16* __restrict__ A,
    const __nv_bfloat16* __restrict__ W,
    const float* __restrict__ bias,
    float* __restrict__ out) {
    extern __shared__ __align__(128) char smem_raw[];
    const uint32_t sbase = smem_u32(smem_raw);

    const int tid = threadIdx.x;
    const int wid = tid >> 5, lane = tid & 31;
    const int wm = wid >> 2;         // 0..3 (M warp, 64 rows each = 256)
    const int wn = wid & 3;          // 0..3 (N warp, 32 cols each = 128)
    const int n0 = (int)(blockIdx.x & 15) * TN;   // N fastest: xq-tile L2 reuse
    const int m0 = (int)(blockIdx.x >> 4) * TM;

    const int lrow = lane & 15;
    const int lhalf = lane >> 4;
    const uint32_t abase = (uint32_t)((wm * 64 + lrow) * RS + lhalf * 16);
    const uint32_t bbase = (uint32_t)((wn * 32 + lrow) * RS + lhalf * 16);

    float acc[4][4][4];
#pragma unroll
    for (int i = 0; i < 4; i++)
#pragma unroll
        for (int j = 0; j < 4; j++)
#pragma unroll
            for (int e = 0; e < 4; e++) acc[i][j][e] = 0.0f;

    load_chunk(sbase + 0 * STAGE_BYTES, A, W, m0, n0, 0 * KC, tid);
    asm volatile("cp.async.commit_group;" ::: "memory");
    load_chunk(sbase + 1 * STAGE_BYTES, A, W, m0, n0, 1 * KC, tid);
    asm volatile("cp.async.commit_group;" ::: "memory");

    uint32_t a[4][4];        // rotating A fragments (current k-step)
    uint32_t b[2][2][4];     // double-buffered B fragments (ks parity)

    for (int i = 0; i < NCHUNK; i++) {
        if (i < NCHUNK - 1) asm volatile("cp.async.wait_group 1;" ::: "memory");
        else                asm volatile("cp.async.wait_group 0;" ::: "memory");
        __syncthreads();

        const uint32_t stA = sbase + (i % STAGES) * STAGE_BYTES;
        const uint32_t stB = stA + STAGE_A_BYTES;

        // Prefetch ks=0 fragments before the cp.async issue burst.
#pragma unroll
        for (int nt = 0; nt < 2; nt++)
            ldsm4(b[0][nt], stB + bbase + (uint32_t)(nt * 16 * RS));
#pragma unroll
        for (int mf = 0; mf < 4; mf++)
            ldsm4(a[mf], stA + abase + (uint32_t)(mf * 16 * RS));

        if (i + 2 < NCHUNK) {
            load_chunk(sbase + ((i + 2) % STAGES) * STAGE_BYTES, A, W,
                       m0, n0, (i + 2) * KC, tid);
            asm volatile("cp.async.commit_group;" ::: "memory");
        }

#pragma unroll
        for (int ks = 0; ks < 4; ks++) {
            const int cur = ks & 1, nxt = cur ^ 1;
            // Prefetch next k-step's B early (used after all 16 mmas below).
            if (ks < 3) {
                uint32_t xoff = (uint32_t)((ks + 1) * 32);
#pragma unroll
                for (int nt = 0; nt < 2; nt++)
                    ldsm4(b[nxt][nt], stB + bbase + (uint32_t)(nt * 16 * RS) + xoff);
            }
#pragma unroll
            for (int mf = 0; mf < 4; mf++) {
                mma16816(acc[mf][0], a[mf], b[cur][0][0], b[cur][0][2]);
                mma16816(acc[mf][1], a[mf], b[cur][0][1], b[cur][0][3]);
                mma16816(acc[mf][2], a[mf], b[cur][1][0], b[cur][1][2]);
                mma16816(acc[mf][3], a[mf], b[cur][1][1], b[cur][1][3]);
                // a[mf] dead for this k-step -> rotate in next k-step's frag.
                if (ks < 3)
                    ldsm4(a[mf], stA + abase +
                          (uint32_t)(mf * 16 * RS + (ks + 1) * 32));
            }
        }
    }

    // Epilogue: f32 acc -> bf16, +bf16 bias, upconvert to f32 store.
    const int qrow = lane >> 2;
    const int qcol = (lane & 3) * 2;
#pragma unroll
    for (int mf = 0; mf < 4; mf++) {
#pragma unroll
        for (int nf = 0; nf < 4; nf++) {
            int col = n0 + wn * 32 + nf * 8 + qcol;
            __nv_bfloat16 b0 = __float2bfloat16(bias[col]);
            __nv_bfloat16 b1 = __float2bfloat16(bias[col + 1]);
            size_t r0 = (size_t)(m0 + wm * 64 + mf * 16 + qrow);
            float2 v0 = make_float2(
                __bfloat162float(__hadd(__float2bfloat16(acc[mf][nf][0]), b0)),
                __bfloat162float(__hadd(__float2bfloat16(acc[mf][nf][1]), b1)));
            float2 v1 = make_float2(
                __bfloat162float(__hadd(__float2bfloat16(acc[mf][nf][2]), b0)),
                __bfloat162float(__hadd(__float2bfloat16(acc[mf][nf][3]), b1)));
            *reinterpret_cast<float2*>(out + r0 * ODIM + col) = v0;
            *reinterpret_cast<float2*>(out + (r0 + 8) * ODIM + col) = v1;
        }
    }
}

// ---------------------------------------------------------------------------
// kernel_launch — inputs identified BY SIZE; all buffers FLOAT32
// ---------------------------------------------------------------------------
extern "C" void kernel_launch(void* const* d_in, const int* in_sizes, int n_in,
                              void* d_out, int out_size) {
    const float* x    = nullptr;
    const float* w    = nullptr;
    const float* bias = nullptr;
    const float* scale = nullptr;
    for (int i = 0; i < n_in; i++) {
        long s = (long)in_sizes[i];
        if (s == (long)NROWS * KDIM)      x     = (const float*)d_in[i];
        else if (s == (long)ODIM * KDIM)  w     = (const float*)d_in[i];
        else if (s == (long)ODIM)         bias  = (const float*)d_in[i];
        else if (s == 1)                  scale = (const float*)d_in[i];
    }
    float* out = (float*)d_out;

    void* xq_ptr = nullptr;
    void* wb_ptr = nullptr;
    cudaGetSymbolAddress(&xq_ptr, g_xq);
    cudaGetSymbolAddress(&wb_ptr, g_wb);

    prep_kernel<<<4096, 256>>>((const float4*)x, (const float4*)w, scale,
                               (uint4*)xq_ptr, (uint4*)wb_ptr);

    cudaFuncSetAttribute(gemm_kernel, cudaFuncAttributeMaxDynamicSharedMemorySize,
                         SMEM_DYN);
    gemm_kernel<<<(NROWS / TM) * (ODIM / TN), THREADS, SMEM_DYN>>>(
        (const __nv_bfloat16*)xq_ptr, (const __nv_bfloat16*)wb_ptr, bias, out);
}

// round 17
// speedup vs baseline: 1.0549x; 1.0549x over previous
#include <cuda_runtime.h>
#include <cuda_bf16.h>
#include <cuda_fp8.h>
#include <cstdint>
#include <cstddef>

// ---------------------------------------------------------------------------
// Problem constants.  ALL in/out buffers are FLOAT32 carriers of bf16 values.
// ---------------------------------------------------------------------------
#define NROWS 32768
#define KDIM  2048
#define ODIM  2048

// GEMM tiling: measured-best config (r11/r15, GEMM 907.6us twice).
// 128x128 CTA tile, 256 threads, 8 warps (2Mx4N, warp tile 64x32),
// 2 CTAs/SM (4 warps/SMSP), 3-stage cp.async, fragment software-pipelining.
#define TM 128
#define TN 128
#define KC 64
#define STAGES 3
#define NCHUNK (KDIM / KC)      // 32
#define THREADS 256

#define RS 144
#define STAGE_A_BYTES (TM * RS)                         // 18432
#define STAGE_B_BYTES (TN * RS)                         // 18432
#define STAGE_BYTES   (STAGE_A_BYTES + STAGE_B_BYTES)   // 36864
#define SMEM_DYN      (STAGES * STAGE_BYTES)            // 110592 (x2 CTAs = 216KB)

// bf16 scratch: quantized x (134MB) and converted W (8MB)
__device__ __nv_bfloat16 g_xq[(size_t)NROWS * KDIM];
__device__ __nv_bfloat16 g_wb[(size_t)ODIM * KDIM];

#define XUNITS ((long)NROWS * KDIM / 8)   // 8388608 8-f32 units
#define WUNITS ((long)ODIM * KDIM / 8)    // 524288
#define TUNITS (XUNITS + WUNITS)

// ---------------------------------------------------------------------------
// helpers
// ---------------------------------------------------------------------------
__device__ __forceinline__ uint32_t smem_u32(const void* p) {
    uint32_t a;
    asm("{ .reg .u64 t; cvta.to.shared.u64 t, %1; cvt.u32.u64 %0, t; }"
        : "=r"(a) : "l"(p));
    return a;
}

__device__ __forceinline__ void cp16(uint32_t dst_smem, const void* src) {
    asm volatile("cp.async.cg.shared.global [%0], [%1], 16;"
                 :: "r"(dst_smem), "l"(__cvta_generic_to_global(src)) : "memory");
}

__device__ __forceinline__ void ldsm4(uint32_t (&r)[4], uint32_t addr) {
    asm volatile("ldmatrix.sync.aligned.m8n8.x4.shared.b16 {%0,%1,%2,%3}, [%4];"
                 : "=r"(r[0]), "=r"(r[1]), "=r"(r[2]), "=r"(r[3]) : "r"(addr));
}

__device__ __forceinline__ void mma16816(float (&d)[4], const uint32_t (&a)[4],
                                         uint32_t b0, uint32_t b1) {
    asm volatile(
        "mma.sync.aligned.m16n8k16.row.col.f32.bf16.bf16.f32 "
        "{%0,%1,%2,%3}, {%4,%5,%6,%7}, {%8,%9}, {%0,%1,%2,%3};"
        : "+f"(d[0]), "+f"(d[1]), "+f"(d[2]), "+f"(d[3])
        : "r"(a[0]), "r"(a[1]), "r"(a[2]), "r"(a[3]), "r"(b0), "r"(b1));
}

// Packed bf16x2 from two floats
__device__ __forceinline__ uint32_t bf16x2_f32(float lo, float hi) {
    uint32_t r;
    asm("cvt.rn.bf16x2.f32 %0, %1, %2;" : "=r"(r) : "f"(hi), "f"(lo));
    return r;
}

// Fast quant of 2 elements (scale == 1.0): f32 -> e4m3(satfinite) -> bf16x2.
__device__ __forceinline__ uint32_t qdq2_s1(float lo, float hi) {
    uint16_t p8;
    asm("cvt.rn.satfinite.e4m3x2.f32 %0, %1, %2;" : "=h"(p8) : "f"(hi), "f"(lo));
    uint32_t h2;
    asm("cvt.rn.f16x2.e4m3x2 %0, %1;" : "=r"(h2) : "h"(p8));
    __half2 h = *reinterpret_cast<__half2*>(&h2);
    return bf16x2_f32(__half2float(__low2half(h)), __half2float(__high2half(h)));
}

// Exact general-scale chain (reference-faithful)
__device__ __forceinline__ __nv_bfloat16 qdq_gen(float v, float sbf, __nv_bfloat16 sb) {
    float xb = __bfloat162float(__float2bfloat16(v));
    float xs = __bfloat162float(__float2bfloat16(xb / sbf));
    __nv_fp8_storage_t q = __nv_cvt_float_to_fp8(xs, __NV_SATFINITE, __NV_E4M3);
    __half_raw hr = __nv_cvt_fp8_to_halfraw(q, __NV_E4M3);
    return __hmul(__float2bfloat16(__half2float(__half(hr))), sb);
}

// ---------------------------------------------------------------------------
// Kernel 1: merged prepass (x quant + W convert), units of 8 f32.
// ---------------------------------------------------------------------------
__global__ void __launch_bounds__(256) prep_kernel(const float4* __restrict__ x,
                                                   const float4* __restrict__ w,
                                                   const float* __restrict__ scale,
                                                   uint4* __restrict__ xq,
                                                   uint4* __restrict__ wb) {
    const __nv_bfloat16 sb = __float2bfloat16(scale[0]);
    const float sbf = __bfloat162float(sb);
    const bool s1 = (sbf == 1.0f);
    long i = (long)blockIdx.x * blockDim.x + threadIdx.x;
    const long stride = (long)gridDim.x * blockDim.x;
    for (; i < TUNITS; i += stride) {
        if (i < XUNITS) {
            float4 v0 = x[2 * i], v1 = x[2 * i + 1];
            uint4 o;
            if (s1) {
                o.x = qdq2_s1(v0.x, v0.y);
                o.y = qdq2_s1(v0.z, v0.w);
                o.z = qdq2_s1(v1.x, v1.y);
                o.w = qdq2_s1(v1.z, v1.w);
            } else {
                __nv_bfloat162 p0 = __halves2bfloat162(qdq_gen(v0.x, sbf, sb),
                                                       qdq_gen(v0.y, sbf, sb));
                __nv_bfloat162 p1 = __halves2bfloat162(qdq_gen(v0.z, sbf, sb),
                                                       qdq_gen(v0.w, sbf, sb));
                __nv_bfloat162 p2 = __halves2bfloat162(qdq_gen(v1.x, sbf, sb),
                                                       qdq_gen(v1.y, sbf, sb));
                __nv_bfloat162 p3 = __halves2bfloat162(qdq_gen(v1.z, sbf, sb),
                                                       qdq_gen(v1.w, sbf, sb));
                o.x = *reinterpret_cast<uint32_t*>(&p0);
                o.y = *reinterpret_cast<uint32_t*>(&p1);
                o.z = *reinterpret_cast<uint32_t*>(&p2);
                o.w = *reinterpret_cast<uint32_t*>(&p3);
            }
            xq[i] = o;
        } else {
            long j = i - XUNITS;
            float4 v0 = w[2 * j], v1 = w[2 * j + 1];
            uint4 o;
            o.x = bf16x2_f32(v0.x, v0.y);
            o.y = bf16x2_f32(v0.z, v0.w);
            o.z = bf16x2_f32(v1.x, v1.y);
            o.w = bf16x2_f32(v1.z, v1.w);
            wb[j] = o;
        }
    }
}

// ---------------------------------------------------------------------------
// Kernel 2: GEMM with fragment software-pipelining:
// B fragments double-buffered across k-steps; A fragments rotated in place.
// ---------------------------------------------------------------------------
__device__ __forceinline__ void load_chunk(uint32_t st, const __nv_bfloat16* A,
                                           const __nv_bfloat16* W,
                                           int m0, int n0, int k0, int tid) {
#pragma unroll
    for (int t = 0; t < 4; t++) {
        int u = tid + t * THREADS;
        int row = u >> 3, c = u & 7;
        cp16(st + (uint32_t)(row * RS + c * 16),
             A + (size_t)(m0 + row) * KDIM + (size_t)(k0 + c * 8));
    }
#pragma unroll
    for (int t = 0; t < 4; t++) {
        int u = tid + t * THREADS;
        int row = u >> 3, c = u & 7;
        cp16(st + STAGE_A_BYTES + (uint32_t)(row * RS + c * 16),
             W + (size_t)(n0 + row) * KDIM + (size_t)(k0 + c * 8));
    }
}

__global__ void __launch_bounds__(THREADS, 2) gemm_kernel(
    const __nv_bfloat16* __restrict__ A,
    const __nv_bfloat16* __restrict__ W,
    const float* __restrict__ bias,
    float* __restrict__ out) {
    extern __shared__ __align__(128) char smem_raw[];
    const uint32_t sbase = smem_u32(smem_raw);

    const int tid = threadIdx.x;
    const int wid = tid >> 5, lane = tid & 31;
    const int wm = wid >> 2;
    const int wn = wid & 3;
    const int n0 = (int)(blockIdx.x & 15) * TN;   // N fastest: xq-tile L2 reuse
    const int m0 = (int)(blockIdx.x >> 4) * TM;

    const int lrow = lane & 15;
    const int lhalf = lane >> 4;
    const uint32_t abase = (uint32_t)((wm * 64 + lrow) * RS + lhalf * 16);
    const uint32_t bbase = (uint32_t)((wn * 32 + lrow) * RS + lhalf * 16);

    float acc[4][4][4];
#pragma unroll
    for (int i = 0; i < 4; i++)
#pragma unroll
        for (int j = 0; j < 4; j++)
#pragma unroll
            for (int e = 0; e < 4; e++) acc[i][j][e] = 0.0f;

    load_chunk(sbase + 0 * STAGE_BYTES, A, W, m0, n0, 0 * KC, tid);
    asm volatile("cp.async.commit_group;" ::: "memory");
    load_chunk(sbase + 1 * STAGE_BYTES, A, W, m0, n0, 1 * KC, tid);
    asm volatile("cp.async.commit_group;" ::: "memory");

    uint32_t a[4][4];        // rotating A fragments (current k-step)
    uint32_t b[2][2][4];     // double-buffered B fragments (ks parity)

    for (int i = 0; i < NCHUNK; i++) {
        if (i < NCHUNK - 1) asm volatile("cp.async.wait_group 1;" ::: "memory");
        else                asm volatile("cp.async.wait_group 0;" ::: "memory");
        __syncthreads();

        const uint32_t stA = sbase + (i % STAGES) * STAGE_BYTES;
        const uint32_t stB = stA + STAGE_A_BYTES;

        // Prefetch ks=0 fragments before the cp.async issue burst.
#pragma unroll
        for (int nt = 0; nt < 2; nt++)
            ldsm4(b[0][nt], stB + bbase + (uint32_t)(nt * 16 * RS));
#pragma unroll
        for (int mf = 0; mf < 4; mf++)
            ldsm4(a[mf], stA + abase + (uint32_t)(mf * 16 * RS));

        if (i + 2 < NCHUNK) {
            load_chunk(sbase + ((i + 2) % STAGES) * STAGE_BYTES, A, W,
                       m0, n0, (i + 2) * KC, tid);
            asm volatile("cp.async.commit_group;" ::: "memory");
        }

#pragma unroll
        for (int ks = 0; ks < 4; ks++) {
            const int cur = ks & 1, nxt = cur ^ 1;
            // Prefetch next k-step's B early (used after all 16 mmas below).
            if (ks < 3) {
                uint32_t xoff = (uint32_t)((ks + 1) * 32);
#pragma unroll
                for (int nt = 0; nt < 2; nt++)
                    ldsm4(b[nxt][nt], stB + bbase + (uint32_t)(nt * 16 * RS) + xoff);
            }
#pragma unroll
            for (int mf = 0; mf < 4; mf++) {
                mma16816(acc[mf][0], a[mf], b[cur][0][0], b[cur][0][2]);
                mma16816(acc[mf][1], a[mf], b[cur][0][1], b[cur][0][3]);
                mma16816(acc[mf][2], a[mf], b[cur][1][0], b[cur][1][2]);
                mma16816(acc[mf][3], a[mf], b[cur][1][1], b[cur][1][3]);
                // a[mf] dead for this k-step -> rotate in next k-step's frag.
                if (ks < 3)
                    ldsm4(a[mf], stA + abase +
                          (uint32_t)(mf * 16 * RS + (ks + 1) * 32));
            }
        }
    }

    // Epilogue: f32 acc -> bf16, +bf16 bias, upconvert to f32 store.
    const int qrow = lane >> 2;
    const int qcol = (lane & 3) * 2;
#pragma unroll
    for (int mf = 0; mf < 4; mf++) {
#pragma unroll
        for (int nf = 0; nf < 4; nf++) {
            int col = n0 + wn * 32 + nf * 8 + qcol;
            __nv_bfloat16 b0 = __float2bfloat16(bias[col]);
            __nv_bfloat16 b1 = __float2bfloat16(bias[col + 1]);
            size_t r0 = (size_t)(m0 + wm * 64 + mf * 16 + qrow);
            float2 v0 = make_float2(
                __bfloat162float(__hadd(__float2bfloat16(acc[mf][nf][0]), b0)),
                __bfloat162float(__hadd(__float2bfloat16(acc[mf][nf][1]), b1)));
            float2 v1 = make_float2(
                __bfloat162float(__hadd(__float2bfloat16(acc[mf][nf][2]), b0)),
                __bfloat162float(__hadd(__float2bfloat16(acc[mf][nf][3]), b1)));
            *reinterpret_cast<float2*>(out + r0 * ODIM + col) = v0;
            *reinterpret_cast<float2*>(out + (r0 + 8) * ODIM + col) = v1;
        }
    }
}

// ---------------------------------------------------------------------------
// kernel_launch — inputs identified BY SIZE; all buffers FLOAT32
// ---------------------------------------------------------------------------
extern "C" void kernel_launch(void* const* d_in, const int* in_sizes, int n_in,
                              void* d_out, int out_size) {
    const float* x    = nullptr;
    const float* w    = nullptr;
    const float* bias = nullptr;
    const float* scale = nullptr;
    for (int i = 0; i < n_in; i++) {
        long s = (long)in_sizes[i];
        if (s == (long)NROWS * KDIM)      x     = (const float*)d_in[i];
        else if (s == (long)ODIM * KDIM)  w     = (const float*)d_in[i];
        else if (s == (long)ODIM)         bias  = (const float*)d_in[i];
        else if (s == 1)                  scale = (const float*)d_in[i];
    }
    float* out = (float*)d_out;

    void* xq_ptr = nullptr;
    void* wb_ptr = nullptr;
    cudaGetSymbolAddress(&xq_ptr, g_xq);
    cudaGetSymbolAddress(&wb_ptr, g_wb);

    prep_kernel<<<8192, 256>>>((const float4*)x, (const float4*)w, scale,
                               (uint4*)xq_ptr, (uint4*)wb_ptr);

    cudaFuncSetAttribute(gemm_kernel, cudaFuncAttributeMaxDynamicSharedMemorySize,
                         SMEM_DYN);
    gemm_kernel<<<(NROWS / TM) * (ODIM / TN), THREADS, SMEM_DYN>>>(
        (const __nv_bfloat16*)xq_ptr, (const __nv_bfloat16*)wb_ptr, bias, out);
}